// round 7
// baseline (speedup 1.0000x reference)
#include <cuda_runtime.h>
#include <cuda_bf16.h>
#include <cstdint>

#define N_ 128
#define D_ 2048
#define C_ 256
#define K_ 8192
#define NJ 3          // Taylor terms j=1..3 (j=0 handled as +256 constant)

#define LOG2E 1.4426950408889634f
#define LN2   0.6931471805599453f
#define INV_T (1.0f / 0.07f)

__device__ float g_penult[N_ * C_];   // zero-init at load; head re-zeroes after use

__device__ __forceinline__ float ex2f_(float x) {
    float y; asm("ex2.approx.f32 %0, %1;" : "=f"(y) : "f"(x)); return y;
}
__device__ __forceinline__ float lg2f_(float x) {
    float y; asm("lg2.approx.f32 %0, %1;" : "=f"(y) : "f"(x)); return y;
}
__device__ __forceinline__ uint32_t su32(const void* p) {
    return (uint32_t)__cvta_generic_to_shared(p);
}
__device__ __forceinline__ uint32_t pack_bf2(float a, float b) {
    __nv_bfloat162 v = __floats2bfloat162_rn(a, b);
    return *reinterpret_cast<uint32_t*>(&v);
}

// ---------------------------------------------------------------------------
// gemm1: g_penult += img @ W_f  (fp32 split-K, 256 CTAs; pure product, no bias)
// ---------------------------------------------------------------------------
__global__ void gemm1_kernel(const float* __restrict__ img,
                             const float* __restrict__ Wf) {
    __shared__ float s_img[128][32];   // 16 KB
    int tid = threadIdx.x;
    int c = blockIdx.x * 64 + (tid & 63);
    int rblk = tid >> 6;
    int d0 = blockIdx.y * 32;

    for (int i = tid; i < 128 * 32; i += 256) {
        int r = i >> 5, dd = i & 31;
        s_img[r][dd] = img[r * D_ + d0 + dd];
    }
    __syncthreads();

    float acc[32];
#pragma unroll
    for (int r = 0; r < 32; r++) acc[r] = 0.0f;

    for (int ds = 0; ds < 32; ds += 4) {
        float w0 = Wf[(d0 + ds + 0) * C_ + c];
        float w1 = Wf[(d0 + ds + 1) * C_ + c];
        float w2 = Wf[(d0 + ds + 2) * C_ + c];
        float w3 = Wf[(d0 + ds + 3) * C_ + c];
#pragma unroll
        for (int r = 0; r < 32; r++) {
            float4 v = *reinterpret_cast<const float4*>(&s_img[rblk * 32 + r][ds]);
            acc[r] = fmaf(v.x, w0, acc[r]);
            acc[r] = fmaf(v.y, w1, acc[r]);
            acc[r] = fmaf(v.z, w2, acc[r]);
            acc[r] = fmaf(v.w, w3, acc[r]);
        }
    }
#pragma unroll
    for (int r = 0; r < 32; r++)
        atomicAdd(&g_penult[(rblk * 32 + r) * C_ + c], acc[r]);
}

// ---------------------------------------------------------------------------
// head: f_logit = (penult + b_f) @ W_c + b_c ; row L2-norm ; l_pos ; labels
//       also re-zeroes g_penult for the next graph replay.
// ---------------------------------------------------------------------------
__global__ void head_kernel(const float* __restrict__ Wc,
                            const float* __restrict__ bc,
                            const float* __restrict__ bf,
                            const float* __restrict__ dist,
                            float* __restrict__ out) {
    __shared__ float sp[C_];
    __shared__ float sred[8];
    int n = blockIdx.x;
    int c = threadIdx.x;

    sp[c] = g_penult[n * C_ + c] + bf[c];
    __syncthreads();
    g_penult[n * C_ + c] = 0.0f;          // reset accumulator for next call

    float acc = bc[c];
#pragma unroll 8
    for (int d = 0; d < C_; d++)
        acc = fmaf(sp[d], Wc[d * C_ + c], acc);

    out[N_ * (K_ + 1) + N_ + n * C_ + c] = acc;   // f_logit
    if (c == 0) out[N_ * (K_ + 1) + n] = 0.0f;    // labels

    float v = acc * acc;
#pragma unroll
    for (int o = 16; o; o >>= 1) v += __shfl_xor_sync(0xffffffffu, v, o);
    if ((c & 31) == 0) sred[c >> 5] = v;
    __syncthreads();
    float ss = sred[0] + sred[1] + sred[2] + sred[3] +
               sred[4] + sred[5] + sred[6] + sred[7];
    __syncthreads();

    float inv = 1.0f / fmaxf(sqrtf(ss), 1e-12f);
    float t = dist[n * C_ + c] * acc * inv;
    float e = ex2f_(t * LOG2E);
#pragma unroll
    for (int o = 16; o; o >>= 1) e += __shfl_xor_sync(0xffffffffu, e, o);
    if ((c & 31) == 0) sred[c >> 5] = e;
    __syncthreads();
    if (c == 0) {
        float s = sred[0] + sred[1] + sred[2] + sred[3] +
                  sred[4] + sred[5] + sred[6] + sred[7];
        out[n * (K_ + 1)] = lg2f_(s) * (LN2 * INV_T);
    }
}

// ---------------------------------------------------------------------------
// lneg: S = sum_j A_j @ B_j (bf16 mma.sync), out = lg2(256+S)*ln2/T
// grid 128 (64-wide k tiles), block 512 (16 warps: 8M x 2N, warp tile 16x32)
// A_j built IN-KERNEL from dist (held in regs as bf16x2); B_j all-resident.
// ---------------------------------------------------------------------------
#define BROW 264
#define AROW 264
#define SM_B   0
#define SM_A   (NJ * 64 * BROW * 2)                 // 101376
#define SM_SS  (SM_A + 128 * AROW * 2)              // 168960
#define SM_INV (SM_SS + 8 * 64 * 4)                 // 171008
#define SM_TOT (SM_INV + 64 * 4)                    // 171264

__global__ __launch_bounds__(512, 1)
void lneg_kernel(const float* __restrict__ dist,
                 const float* __restrict__ q,
                 float* __restrict__ out) {
    extern __shared__ char smem[];
    __nv_bfloat16* Bs = (__nv_bfloat16*)(smem + SM_B);
    __nv_bfloat16* As = (__nv_bfloat16*)(smem + SM_A);
    float* sspart = (float*)(smem + SM_SS);
    float* invn   = (float*)(smem + SM_INV);

    int tid = threadIdx.x;
    int k0 = blockIdx.x * 64;
    int kx = tid & 63, cg = tid >> 6;   // cg 0..7

    // ---- load this thread's dist slice into regs as bf16x2 (row am, 64 c's) ----
    int am = tid & 127;                 // A row
    int ac = (tid >> 7) * 64;           // A col base (chunk)
    __nv_bfloat162 d2[32];
    {
        const float4* dp = (const float4*)(dist + am * C_ + ac);
#pragma unroll
        for (int i = 0; i < 16; i++) {
            float4 v = dp[i];
            d2[2 * i]     = __floats2bfloat162_rn(v.x, v.y);
            d2[2 * i + 1] = __floats2bfloat162_rn(v.z, v.w);
        }
    }

    // ---- column sum-of-squares for this 64-column slab of q ----
    float ss = 0.0f;
    for (int c = cg; c < C_; c += 8) {
        float v = q[c * K_ + k0 + kx];
        ss = fmaf(v, v, ss);
    }
    sspart[cg * 64 + kx] = ss;
    __syncthreads();
    if (tid < 64) {
        float s = 0.0f;
#pragma unroll
        for (int g = 0; g < 8; g++) s += sspart[g * 64 + tid];
        invn[tid] = 1.0f / fmaxf(sqrtf(s), 1e-12f);
    }
    __syncthreads();

    // ---- build B_j = b^j (bf16), layout [j][kcol][c] ----
    float iv = invn[kx];
#pragma unroll
    for (int i = 0; i < 16; ++i) {
        int c = cg * 2 + i * 16;
        float b0 = q[c * K_ + k0 + kx] * iv;
        float b1 = q[(c + 1) * K_ + k0 + kx] * iv;
        float p0 = b0, p1 = b1;
        *(uint32_t*)(Bs + 0 * 64 * BROW + kx * BROW + c) = pack_bf2(p0, p1);
        p0 *= b0; p1 *= b1;
        *(uint32_t*)(Bs + 1 * 64 * BROW + kx * BROW + c) = pack_bf2(p0, p1);
        p0 *= b0; p1 *= b1;
        *(uint32_t*)(Bs + 2 * 64 * BROW + kx * BROW + c) = pack_bf2(p0, p1);
    }

    int warp = tid >> 5, lane = tid & 31;
    int mrow = (warp >> 1) * 16;     // 8 warps along M
    int ncol = (warp & 1) * 32;      // 2 warps along N

    float acc[4][4];
#pragma unroll
    for (int nt = 0; nt < 4; nt++)
#pragma unroll
        for (int i = 0; i < 4; i++) acc[nt][i] = 0.0f;

    uint32_t Ab = su32(As);
    const __nv_bfloat162 c05 = __float2bfloat162_rn(0.5f);
    const __nv_bfloat162 c16 = __float2bfloat162_rn(1.0f / 6.0f);

    for (int j = 0; j < NJ; ++j) {
        __syncthreads();   // B build done (j=0) / previous A consumption done
        // build A_j [128 x 256] from d2 regs (8 x STS.128 per thread)
#pragma unroll
        for (int g = 0; g < 8; ++g) {
            uint4 v;
            __nv_bfloat162* pv = (__nv_bfloat162*)&v;
#pragma unroll
            for (int i = 0; i < 4; ++i) {
                __nv_bfloat162 d = d2[g * 4 + i];
                if (j == 0)      pv[i] = d;
                else if (j == 1) pv[i] = __hmul2(__hmul2(d, d), c05);
                else             pv[i] = __hmul2(__hmul2(__hmul2(d, d), d), c16);
            }
            *reinterpret_cast<uint4*>(As + am * AROW + ac + g * 8) = v;
        }
        __syncthreads();

        uint32_t Bj = su32(Bs) + (uint32_t)(j * 64 * BROW * 2);
#pragma unroll
        for (int kt = 0; kt < 16; ++kt) {
            // A: one x4 (16 rows x 16 k)
            uint32_t a[4];
            {
                uint32_t addr = Ab + (uint32_t)(((mrow + (lane & 15)) * AROW
                                                 + kt * 16 + (lane >> 4) * 8) * 2);
                asm volatile("ldmatrix.sync.aligned.m8n8.x4.shared.b16 {%0,%1,%2,%3}, [%4];"
                             : "=r"(a[0]), "=r"(a[1]), "=r"(a[2]), "=r"(a[3])
                             : "r"(addr));
            }
            // B: two x4 loads, each covering 16 n x 16 k
            uint32_t bq[2][4];
#pragma unroll
            for (int p = 0; p < 2; ++p) {
                int grp = lane >> 3;
                int nb = (grp >> 1) * 8, kb = (grp & 1) * 8;
                int row = ncol + p * 16 + nb + (lane & 7);
                uint32_t addr = Bj + (uint32_t)((row * BROW + kt * 16 + kb) * 2);
                asm volatile("ldmatrix.sync.aligned.m8n8.x4.shared.b16 {%0,%1,%2,%3}, [%4];"
                             : "=r"(bq[p][0]), "=r"(bq[p][1]), "=r"(bq[p][2]), "=r"(bq[p][3])
                             : "r"(addr));
            }
#pragma unroll
            for (int nt = 0; nt < 4; ++nt) {
                uint32_t b0 = bq[nt >> 1][(nt & 1) * 2];
                uint32_t b1 = bq[nt >> 1][(nt & 1) * 2 + 1];
                asm volatile(
                    "mma.sync.aligned.m16n8k16.row.col.f32.bf16.bf16.f32 "
                    "{%0,%1,%2,%3}, {%4,%5,%6,%7}, {%8,%9}, {%0,%1,%2,%3};"
                    : "+f"(acc[nt][0]), "+f"(acc[nt][1]),
                      "+f"(acc[nt][2]), "+f"(acc[nt][3])
                    : "r"(a[0]), "r"(a[1]), "r"(a[2]), "r"(a[3]),
                      "r"(b0), "r"(b1));
            }
        }
    }

    // epilogue: out = lg2(256 + S) * ln2 / T
    const float sc = LN2 * INV_T;
#pragma unroll
    for (int nt = 0; nt < 4; ++nt) {
        int r = mrow + (lane >> 2);
        int col = k0 + ncol + nt * 8 + (lane & 3) * 2;
        int base = r * (K_ + 1) + 1 + col;
        out[base]     = lg2f_(256.0f + acc[nt][0]) * sc;
        out[base + 1] = lg2f_(256.0f + acc[nt][1]) * sc;
        int base2 = (r + 8) * (K_ + 1) + 1 + col;
        out[base2]     = lg2f_(256.0f + acc[nt][2]) * sc;
        out[base2 + 1] = lg2f_(256.0f + acc[nt][3]) * sc;
    }
}

extern "C" void kernel_launch(void* const* d_in, const int* in_sizes, int n_in,
                              void* d_out, int out_size) {
    const float* img  = (const float*)d_in[0];
    const float* Wf   = (const float*)d_in[1];
    const float* bf   = (const float*)d_in[2];
    const float* Wc   = (const float*)d_in[3];
    const float* bc   = (const float*)d_in[4];
    const float* dist = (const float*)d_in[5];
    const float* q    = (const float*)d_in[6];
    float* out = (float*)d_out;

    // One-time host resources (created on the uncaptured correctness call).
    static cudaStream_t s1 = nullptr;
    static cudaEvent_t ev0 = nullptr, ev1 = nullptr;
    if (s1 == nullptr) {
        cudaStreamCreateWithFlags(&s1, cudaStreamNonBlocking);
        cudaEventCreateWithFlags(&ev0, cudaEventDisableTiming);
        cudaEventCreateWithFlags(&ev1, cudaEventDisableTiming);
        cudaFuncSetAttribute(lneg_kernel,
                             cudaFuncAttributeMaxDynamicSharedMemorySize, SM_TOT);
    }

    // fork: {lneg on main} || {gemm1 -> head on s1} -> join
    cudaEventRecord(ev0, 0);
    cudaStreamWaitEvent(s1, ev0, 0);
    lneg_kernel<<<K_ / 64, 512, SM_TOT>>>(dist, q, out);
    gemm1_kernel<<<dim3(4, 64), 256, 0, s1>>>(img, Wf);
    head_kernel<<<N_, 256, 0, s1>>>(Wc, bc, bf, dist, out);
    cudaEventRecord(ev1, s1);
    cudaStreamWaitEvent(0, ev1, 0);
}

// round 8
// speedup vs baseline: 1.0997x; 1.0997x over previous
#include <cuda_runtime.h>
#include <cuda_bf16.h>
#include <cstdint>

#define N_ 128
#define D_ 2048
#define C_ 256
#define K_ 8192
#define NJ 3          // Taylor terms j=1..3 (j=0 handled as +256 constant)

#define LOG2E 1.4426950408889634f
#define LN2   0.6931471805599453f
#define INV_T (1.0f / 0.07f)

__device__ float g_penult[N_ * C_];
__device__ __nv_bfloat16 g_A[NJ * N_ * C_];   // A_j[n][c] = dist^j / j!

__device__ __forceinline__ float ex2f_(float x) {
    float y; asm("ex2.approx.f32 %0, %1;" : "=f"(y) : "f"(x)); return y;
}
__device__ __forceinline__ float lg2f_(float x) {
    float y; asm("lg2.approx.f32 %0, %1;" : "=f"(y) : "f"(x)); return y;
}
__device__ __forceinline__ uint32_t su32(const void* p) {
    return (uint32_t)__cvta_generic_to_shared(p);
}
__device__ __forceinline__ uint32_t pack_bf2(float a, float b) {
    __nv_bfloat162 v = __floats2bfloat162_rn(a, b);
    return *reinterpret_cast<uint32_t*>(&v);
}

// ---------------------------------------------------------------------------
// prep: A powers (bf16), penult = bias, labels = 0   (same as R6)
// ---------------------------------------------------------------------------
__global__ void prep_kernel(const float* __restrict__ dist,
                            const float* __restrict__ bf,
                            float* __restrict__ out) {
    int n = blockIdx.x, c = threadIdx.x;
    float d = dist[n * C_ + c];
    float p = d;
    g_A[(0 * N_ + n) * C_ + c] = __float2bfloat16(p);
    p *= d;
    g_A[(1 * N_ + n) * C_ + c] = __float2bfloat16(p * 0.5f);
    p *= d;
    g_A[(2 * N_ + n) * C_ + c] = __float2bfloat16(p * (1.0f / 6.0f));
    g_penult[n * C_ + c] = bf[c];
    if (c == 0) out[N_ * (K_ + 1) + n] = 0.0f;   // labels
}

// ---------------------------------------------------------------------------
// gemm1: penult += img @ W_f  (fp32 split-K, 256 CTAs)   (same as R6)
// ---------------------------------------------------------------------------
__global__ void gemm1_kernel(const float* __restrict__ img,
                             const float* __restrict__ Wf) {
    __shared__ float s_img[128][32];   // 16 KB
    int tid = threadIdx.x;
    int c = blockIdx.x * 64 + (tid & 63);
    int rblk = tid >> 6;
    int d0 = blockIdx.y * 32;

    for (int i = tid; i < 128 * 32; i += 256) {
        int r = i >> 5, dd = i & 31;
        s_img[r][dd] = img[r * D_ + d0 + dd];
    }
    __syncthreads();

    float acc[32];
#pragma unroll
    for (int r = 0; r < 32; r++) acc[r] = 0.0f;

    for (int ds = 0; ds < 32; ds += 4) {
        float w0 = Wf[(d0 + ds + 0) * C_ + c];
        float w1 = Wf[(d0 + ds + 1) * C_ + c];
        float w2 = Wf[(d0 + ds + 2) * C_ + c];
        float w3 = Wf[(d0 + ds + 3) * C_ + c];
#pragma unroll
        for (int r = 0; r < 32; r++) {
            float4 v = *reinterpret_cast<const float4*>(&s_img[rblk * 32 + r][ds]);
            acc[r] = fmaf(v.x, w0, acc[r]);
            acc[r] = fmaf(v.y, w1, acc[r]);
            acc[r] = fmaf(v.z, w2, acc[r]);
            acc[r] = fmaf(v.w, w3, acc[r]);
        }
    }
#pragma unroll
    for (int r = 0; r < 32; r++)
        atomicAdd(&g_penult[(rblk * 32 + r) * C_ + c], acc[r]);
}

// ---------------------------------------------------------------------------
// head: f_logit + row norm + l_pos (fp32)   (same as R6)
// ---------------------------------------------------------------------------
__global__ void head_kernel(const float* __restrict__ Wc,
                            const float* __restrict__ bc,
                            const float* __restrict__ dist,
                            float* __restrict__ out) {
    __shared__ float sp[C_];
    __shared__ float sred[8];
    int n = blockIdx.x;
    int c = threadIdx.x;

    sp[c] = g_penult[n * C_ + c];
    __syncthreads();

    float acc = bc[c];
#pragma unroll 8
    for (int d = 0; d < C_; d++)
        acc = fmaf(sp[d], Wc[d * C_ + c], acc);

    out[N_ * (K_ + 1) + N_ + n * C_ + c] = acc;

    float v = acc * acc;
#pragma unroll
    for (int o = 16; o; o >>= 1) v += __shfl_xor_sync(0xffffffffu, v, o);
    if ((c & 31) == 0) sred[c >> 5] = v;
    __syncthreads();
    float ss = sred[0] + sred[1] + sred[2] + sred[3] +
               sred[4] + sred[5] + sred[6] + sred[7];
    __syncthreads();

    float inv = 1.0f / fmaxf(sqrtf(ss), 1e-12f);
    float t = dist[n * C_ + c] * acc * inv;
    float e = ex2f_(t * LOG2E);
#pragma unroll
    for (int o = 16; o; o >>= 1) e += __shfl_xor_sync(0xffffffffu, e, o);
    if ((c & 31) == 0) sred[c >> 5] = e;
    __syncthreads();
    if (c == 0) {
        float s = sred[0] + sred[1] + sred[2] + sred[3] +
                  sred[4] + sred[5] + sred[6] + sred[7];
        out[n * (K_ + 1)] = lg2f_(s) * (LN2 * INV_T);
    }
}

// ---------------------------------------------------------------------------
// lneg v3: grid 256 (32-wide k tiles), block 256 (8 warps: 4M x 2N),
//          2 CTAs/SM. XOR-swizzled flat smem tiles (no padding):
//   B: [j][n(32)][c(256)] rows of 512B, chunk swizz ch^(n&7)   -> 48 KB
//   A: [m(128)][c(256)]   rows of 512B, chunk swizz ch^(m&7)   -> 64 KB
//   ss/inv alias into A region (consumed before A staged).
//   kt loop software-pipelined (frags for kt+1 loaded during kt MMAs).
// ---------------------------------------------------------------------------
#define SMB   0
#define SMA   49152
#define SMTOT 114688

__device__ __forceinline__ void ld_a_x4(uint32_t addr, uint32_t* a) {
    asm volatile("ldmatrix.sync.aligned.m8n8.x4.shared.b16 {%0,%1,%2,%3}, [%4];"
                 : "=r"(a[0]), "=r"(a[1]), "=r"(a[2]), "=r"(a[3]) : "r"(addr));
}

__global__ __launch_bounds__(256, 2)
void lneg_kernel(const float* __restrict__ q,
                 float* __restrict__ out) {
    extern __shared__ char smem[];
    uint32_t sb = su32(smem);
    int tid = threadIdx.x;
    int kx = tid & 31, cg = tid >> 5;     // kx: k-col, cg: 32-wide c-chunk (0..7)
    int k0 = blockIdx.x * 32;

    // ---- load q slab column-slice into regs; per-group sum of squares ----
    float qv[32];
    float ss = 0.0f;
    {
        const float* qp = q + (size_t)(cg * 32) * K_ + k0 + kx;
#pragma unroll
        for (int i = 0; i < 32; i++) {
            qv[i] = qp[(size_t)i * K_];
            ss = fmaf(qv[i], qv[i], ss);
        }
    }
    float* ssp = (float*)(smem + SMA);          // alias: used before A staged
    float* invp = (float*)(smem + SMA + 1024);
    ssp[cg * 32 + kx] = ss;
    __syncthreads();
    if (tid < 32) {
        float s = 0.0f;
#pragma unroll
        for (int g = 0; g < 8; g++) s += ssp[g * 32 + tid];
        invp[tid] = 1.0f / fmaxf(sqrtf(s), 1e-12f);
    }
    __syncthreads();

    // ---- build B_j = b^j (bf16) into swizzled tiles ----
    {
        float iv = invp[kx];
#pragma unroll
        for (int i = 0; i < 16; ++i) {
            int c2 = cg * 32 + i * 2;
            float b0 = qv[2 * i] * iv, b1 = qv[2 * i + 1] * iv;
            float p0 = b0, p1 = b1;
            uint32_t off = (uint32_t)(kx * 512 + (((c2 >> 3) ^ (kx & 7)) << 4)
                                      + (c2 & 7) * 2);
#pragma unroll
            for (int j = 0; j < NJ; j++) {
                *(uint32_t*)(smem + SMB + j * 16384 + off) = pack_bf2(p0, p1);
                p0 *= b0; p1 *= b1;
            }
        }
    }

    int warp = tid >> 5, lane = tid & 31;
    int mrow = (warp >> 1) * 32;   // 4 warps along M (32 rows each)
    int ncol = (warp & 1) * 16;    // 2 warps along N (16 cols each)

    float acc[2][2][4];
#pragma unroll
    for (int mt = 0; mt < 2; mt++)
#pragma unroll
        for (int nt = 0; nt < 2; nt++)
#pragma unroll
            for (int i = 0; i < 4; i++) acc[mt][nt][i] = 0.0f;

    // precomputed ldmatrix lane addressing
    int a_row0 = mrow + (lane & 15);
    int a_chL  = lane >> 4;                  // 0/1 -> k-halves
    int t4 = lane >> 3;
    int b_row = ncol + ((t4 >> 1) << 3) + (lane & 7);
    int b_chL = t4 & 1;

    for (int j = 0; j < NJ; ++j) {
        __syncthreads();   // B build done (j=0) / prior A consumption done
        // stage A_j [128 x 256] -> swizzled flat tile (16 x 16B per thread)
        const uint4* Asrc = (const uint4*)(g_A + (size_t)j * N_ * C_);
#pragma unroll
        for (int t = 0; t < 16; ++t) {
            int lin = t * 256 + tid;          // 0..4095 uint4s
            int m = lin >> 5;
            int ch = lin & 31;
            *(uint4*)(smem + SMA + m * 512 + ((ch ^ (m & 7)) << 4)) = Asrc[lin];
        }
        __syncthreads();

        uint32_t Ab = sb + SMA;
        uint32_t Bb = sb + SMB + (uint32_t)(j * 16384);

        uint32_t a_c[2][4], b_c[4], a_n[2][4], b_n[4];
        // preload kt = 0
#pragma unroll
        for (int mt = 0; mt < 2; ++mt) {
            int row = a_row0 + mt * 16;
            ld_a_x4(Ab + row * 512 + (((a_chL ^ (row & 7)) << 4)), a_c[mt]);
        }
        ld_a_x4(Bb + b_row * 512 + (((b_chL ^ (b_row & 7)) << 4)), b_c);

#pragma unroll
        for (int kt = 0; kt < 16; ++kt) {
            if (kt < 15) {
                int ch = (kt + 1) * 2;
#pragma unroll
                for (int mt = 0; mt < 2; ++mt) {
                    int row = a_row0 + mt * 16;
                    ld_a_x4(Ab + row * 512 + ((((ch + a_chL) ^ (row & 7)) << 4)), a_n[mt]);
                }
                ld_a_x4(Bb + b_row * 512 + ((((ch + b_chL) ^ (b_row & 7)) << 4)), b_n);
            }
#pragma unroll
            for (int mt = 0; mt < 2; ++mt)
#pragma unroll
                for (int nt = 0; nt < 2; ++nt)
                    asm volatile(
                        "mma.sync.aligned.m16n8k16.row.col.f32.bf16.bf16.f32 "
                        "{%0,%1,%2,%3}, {%4,%5,%6,%7}, {%8,%9}, {%0,%1,%2,%3};"
                        : "+f"(acc[mt][nt][0]), "+f"(acc[mt][nt][1]),
                          "+f"(acc[mt][nt][2]), "+f"(acc[mt][nt][3])
                        : "r"(a_c[mt][0]), "r"(a_c[mt][1]),
                          "r"(a_c[mt][2]), "r"(a_c[mt][3]),
                          "r"(b_c[nt * 2]), "r"(b_c[nt * 2 + 1]));
            if (kt < 15) {
#pragma unroll
                for (int mt = 0; mt < 2; ++mt)
#pragma unroll
                    for (int i = 0; i < 4; ++i) a_c[mt][i] = a_n[mt][i];
#pragma unroll
                for (int i = 0; i < 4; ++i) b_c[i] = b_n[i];
            }
        }
    }

    // ---- epilogue: out = lg2(256 + S) * ln2 / T ----
    const float sc = LN2 * INV_T;
#pragma unroll
    for (int mt = 0; mt < 2; ++mt) {
#pragma unroll
        for (int nt = 0; nt < 2; ++nt) {
            int r = mrow + mt * 16 + (lane >> 2);
            int col = k0 + ncol + nt * 8 + (lane & 3) * 2;
            int base = r * (K_ + 1) + 1 + col;
            out[base]     = lg2f_(256.0f + acc[mt][nt][0]) * sc;
            out[base + 1] = lg2f_(256.0f + acc[mt][nt][1]) * sc;
            int base2 = (r + 8) * (K_ + 1) + 1 + col;
            out[base2]     = lg2f_(256.0f + acc[mt][nt][2]) * sc;
            out[base2 + 1] = lg2f_(256.0f + acc[mt][nt][3]) * sc;
        }
    }
}

extern "C" void kernel_launch(void* const* d_in, const int* in_sizes, int n_in,
                              void* d_out, int out_size) {
    const float* img  = (const float*)d_in[0];
    const float* Wf   = (const float*)d_in[1];
    const float* bf   = (const float*)d_in[2];
    const float* Wc   = (const float*)d_in[3];
    const float* bc   = (const float*)d_in[4];
    const float* dist = (const float*)d_in[5];
    const float* q    = (const float*)d_in[6];
    float* out = (float*)d_out;

    // One-time host resources (created on the uncaptured correctness call).
    static cudaStream_t s1 = nullptr;
    static cudaEvent_t ev0 = nullptr, ev1 = nullptr;
    if (s1 == nullptr) {
        cudaStreamCreateWithFlags(&s1, cudaStreamNonBlocking);
        cudaEventCreateWithFlags(&ev0, cudaEventDisableTiming);
        cudaEventCreateWithFlags(&ev1, cudaEventDisableTiming);
        cudaFuncSetAttribute(lneg_kernel,
                             cudaFuncAttributeMaxDynamicSharedMemorySize, SMTOT);
    }

    // prep -> fork: {lneg on main} || {gemm1 -> head on s1} -> join
    prep_kernel<<<N_, C_>>>(dist, bf, out);
    cudaEventRecord(ev0, 0);
    cudaStreamWaitEvent(s1, ev0, 0);
    lneg_kernel<<<K_ / 32, 256, SMTOT>>>(q, out);
    gemm1_kernel<<<dim3(4, 64), 256, 0, s1>>>(img, Wf);
    head_kernel<<<N_, 256, 0, s1>>>(Wc, bc, dist, out);
    cudaEventRecord(ev1, s1);
    cudaStreamWaitEvent(0, ev1, 0);
}

// round 9
// speedup vs baseline: 1.1512x; 1.0468x over previous
#include <cuda_runtime.h>
#include <cuda_bf16.h>
#include <cstdint>

#define N_ 128
#define D_ 2048
#define C_ 256
#define K_ 8192
#define NJ 3          // Taylor terms j=1..3 (j=0 handled as +256 constant)

#define LOG2E 1.4426950408889634f
#define LN2   0.6931471805599453f
#define INV_T (1.0f / 0.07f)

__device__ float g_penult[N_ * C_];           // zero-init; head re-zeroes after use
__device__ __nv_bfloat16 g_A[NJ * N_ * C_];   // A_j[n][c] = dist^j / j!

__device__ __forceinline__ float ex2f_(float x) {
    float y; asm("ex2.approx.f32 %0, %1;" : "=f"(y) : "f"(x)); return y;
}
__device__ __forceinline__ float lg2f_(float x) {
    float y; asm("lg2.approx.f32 %0, %1;" : "=f"(y) : "f"(x)); return y;
}
__device__ __forceinline__ uint32_t su32(const void* p) {
    return (uint32_t)__cvta_generic_to_shared(p);
}
__device__ __forceinline__ uint32_t pack_bf2(float a, float b) {
    __nv_bfloat162 v = __floats2bfloat162_rn(a, b);
    return *reinterpret_cast<uint32_t*>(&v);
}

// ---------------------------------------------------------------------------
// prep: A powers (bf16), labels = 0   (penult untouched -> gemm1 has no deps)
// ---------------------------------------------------------------------------
__global__ void prep_kernel(const float* __restrict__ dist,
                            float* __restrict__ out) {
    int n = blockIdx.x, c = threadIdx.x;
    float d = dist[n * C_ + c];
    float p = d;
    g_A[(0 * N_ + n) * C_ + c] = __float2bfloat16(p);
    p *= d;
    g_A[(1 * N_ + n) * C_ + c] = __float2bfloat16(p * 0.5f);
    p *= d;
    g_A[(2 * N_ + n) * C_ + c] = __float2bfloat16(p * (1.0f / 6.0f));
    if (c == 0) out[N_ * (K_ + 1) + n] = 0.0f;   // labels
}

// ---------------------------------------------------------------------------
// gemm1: g_penult += img @ W_f  (fp32 split-K, 256 CTAs; pure product)
// ---------------------------------------------------------------------------
__global__ void gemm1_kernel(const float* __restrict__ img,
                             const float* __restrict__ Wf) {
    __shared__ float s_img[128][32];   // 16 KB
    int tid = threadIdx.x;
    int c = blockIdx.x * 64 + (tid & 63);
    int rblk = tid >> 6;
    int d0 = blockIdx.y * 32;

    for (int i = tid; i < 128 * 32; i += 256) {
        int r = i >> 5, dd = i & 31;
        s_img[r][dd] = img[r * D_ + d0 + dd];
    }
    __syncthreads();

    float acc[32];
#pragma unroll
    for (int r = 0; r < 32; r++) acc[r] = 0.0f;

    for (int ds = 0; ds < 32; ds += 4) {
        float w0 = Wf[(d0 + ds + 0) * C_ + c];
        float w1 = Wf[(d0 + ds + 1) * C_ + c];
        float w2 = Wf[(d0 + ds + 2) * C_ + c];
        float w3 = Wf[(d0 + ds + 3) * C_ + c];
#pragma unroll
        for (int r = 0; r < 32; r++) {
            float4 v = *reinterpret_cast<const float4*>(&s_img[rblk * 32 + r][ds]);
            acc[r] = fmaf(v.x, w0, acc[r]);
            acc[r] = fmaf(v.y, w1, acc[r]);
            acc[r] = fmaf(v.z, w2, acc[r]);
            acc[r] = fmaf(v.w, w3, acc[r]);
        }
    }
#pragma unroll
    for (int r = 0; r < 32; r++)
        atomicAdd(&g_penult[(rblk * 32 + r) * C_ + c], acc[r]);
}

// ---------------------------------------------------------------------------
// head v2: split-K x4, block 1024. f_logit = (penult+b_f) @ W_c + b_c ;
//          row L2-norm ; l_pos. Re-zeroes g_penult for graph replay.
// ---------------------------------------------------------------------------
__global__ __launch_bounds__(1024, 1)
void head_kernel(const float* __restrict__ Wc,
                 const float* __restrict__ bc,
                 const float* __restrict__ bf,
                 const float* __restrict__ dist,
                 float* __restrict__ out) {
    __shared__ float sp[C_];
    __shared__ float part[3][C_];
    __shared__ float sred[8];
    int n = blockIdx.x;
    int tid = threadIdx.x;
    int ks = tid >> 8;        // 0..3 (64 d's each)
    int c = tid & 255;

    if (ks == 0) sp[c] = g_penult[n * C_ + c] + bf[c];
    __syncthreads();
    if (ks == 0) g_penult[n * C_ + c] = 0.0f;   // reset accumulator

    float acc = 0.0f;
    int d0 = ks * 64;
#pragma unroll 8
    for (int d = 0; d < 64; d++)
        acc = fmaf(sp[d0 + d], Wc[(d0 + d) * C_ + c], acc);

    if (ks) part[ks - 1][c] = acc;
    __syncthreads();
    if (ks != 0) return;

    acc += bc[c] + part[0][c] + part[1][c] + part[2][c];

    out[N_ * (K_ + 1) + N_ + n * C_ + c] = acc;   // f_logit

    float v = acc * acc;
#pragma unroll
    for (int o = 16; o; o >>= 1) v += __shfl_xor_sync(0xffffffffu, v, o);
    if ((c & 31) == 0) sred[c >> 5] = v;
    __syncthreads();
    float ss = sred[0] + sred[1] + sred[2] + sred[3] +
               sred[4] + sred[5] + sred[6] + sred[7];
    __syncthreads();

    float inv = 1.0f / fmaxf(sqrtf(ss), 1e-12f);
    float t = dist[n * C_ + c] * acc * inv;
    float e = ex2f_(t * LOG2E);
#pragma unroll
    for (int o = 16; o; o >>= 1) e += __shfl_xor_sync(0xffffffffu, e, o);
    if ((c & 31) == 0) sred[c >> 5] = e;
    __syncthreads();
    if (c == 0) {
        float s = sred[0] + sred[1] + sred[2] + sred[3] +
                  sred[4] + sred[5] + sred[6] + sred[7];
        out[n * (K_ + 1)] = lg2f_(s) * (LN2 * INV_T);
    }
}

// ---------------------------------------------------------------------------
// lneg v3 (unchanged from R8): grid 256 (32-wide k tiles), block 256,
// 2 CTAs/SM, XOR-swizzled flat tiles, pipelined kt loop.
// ---------------------------------------------------------------------------
#define SMB   0
#define SMA   49152
#define SMTOT 114688

__device__ __forceinline__ void ld_a_x4(uint32_t addr, uint32_t* a) {
    asm volatile("ldmatrix.sync.aligned.m8n8.x4.shared.b16 {%0,%1,%2,%3}, [%4];"
                 : "=r"(a[0]), "=r"(a[1]), "=r"(a[2]), "=r"(a[3]) : "r"(addr));
}

__global__ __launch_bounds__(256, 2)
void lneg_kernel(const float* __restrict__ q,
                 float* __restrict__ out) {
    extern __shared__ char smem[];
    uint32_t sb = su32(smem);
    int tid = threadIdx.x;
    int kx = tid & 31, cg = tid >> 5;
    int k0 = blockIdx.x * 32;

    float qv[32];
    float ss = 0.0f;
    {
        const float* qp = q + (size_t)(cg * 32) * K_ + k0 + kx;
#pragma unroll
        for (int i = 0; i < 32; i++) {
            qv[i] = qp[(size_t)i * K_];
            ss = fmaf(qv[i], qv[i], ss);
        }
    }
    float* ssp = (float*)(smem + SMA);
    float* invp = (float*)(smem + SMA + 1024);
    ssp[cg * 32 + kx] = ss;
    __syncthreads();
    if (tid < 32) {
        float s = 0.0f;
#pragma unroll
        for (int g = 0; g < 8; g++) s += ssp[g * 32 + tid];
        invp[tid] = 1.0f / fmaxf(sqrtf(s), 1e-12f);
    }
    __syncthreads();

    {
        float iv = invp[kx];
#pragma unroll
        for (int i = 0; i < 16; ++i) {
            int c2 = cg * 32 + i * 2;
            float b0 = qv[2 * i] * iv, b1 = qv[2 * i + 1] * iv;
            float p0 = b0, p1 = b1;
            uint32_t off = (uint32_t)(kx * 512 + (((c2 >> 3) ^ (kx & 7)) << 4)
                                      + (c2 & 7) * 2);
#pragma unroll
            for (int j = 0; j < NJ; j++) {
                *(uint32_t*)(smem + SMB + j * 16384 + off) = pack_bf2(p0, p1);
                p0 *= b0; p1 *= b1;
            }
        }
    }

    int warp = tid >> 5, lane = tid & 31;
    int mrow = (warp >> 1) * 32;
    int ncol = (warp & 1) * 16;

    float acc[2][2][4];
#pragma unroll
    for (int mt = 0; mt < 2; mt++)
#pragma unroll
        for (int nt = 0; nt < 2; nt++)
#pragma unroll
            for (int i = 0; i < 4; i++) acc[mt][nt][i] = 0.0f;

    int a_row0 = mrow + (lane & 15);
    int a_chL  = lane >> 4;
    int t4 = lane >> 3;
    int b_row = ncol + ((t4 >> 1) << 3) + (lane & 7);
    int b_chL = t4 & 1;

    for (int j = 0; j < NJ; ++j) {
        __syncthreads();
        const uint4* Asrc = (const uint4*)(g_A + (size_t)j * N_ * C_);
#pragma unroll
        for (int t = 0; t < 16; ++t) {
            int lin = t * 256 + tid;
            int m = lin >> 5;
            int ch = lin & 31;
            *(uint4*)(smem + SMA + m * 512 + ((ch ^ (m & 7)) << 4)) = Asrc[lin];
        }
        __syncthreads();

        uint32_t Ab = sb + SMA;
        uint32_t Bb = sb + SMB + (uint32_t)(j * 16384);

        uint32_t a_c[2][4], b_c[4], a_n[2][4], b_n[4];
#pragma unroll
        for (int mt = 0; mt < 2; ++mt) {
            int row = a_row0 + mt * 16;
            ld_a_x4(Ab + row * 512 + (((a_chL ^ (row & 7)) << 4)), a_c[mt]);
        }
        ld_a_x4(Bb + b_row * 512 + (((b_chL ^ (b_row & 7)) << 4)), b_c);

#pragma unroll
        for (int kt = 0; kt < 16; ++kt) {
            if (kt < 15) {
                int ch = (kt + 1) * 2;
#pragma unroll
                for (int mt = 0; mt < 2; ++mt) {
                    int row = a_row0 + mt * 16;
                    ld_a_x4(Ab + row * 512 + ((((ch + a_chL) ^ (row & 7)) << 4)), a_n[mt]);
                }
                ld_a_x4(Bb + b_row * 512 + ((((ch + b_chL) ^ (b_row & 7)) << 4)), b_n);
            }
#pragma unroll
            for (int mt = 0; mt < 2; ++mt)
#pragma unroll
                for (int nt = 0; nt < 2; ++nt)
                    asm volatile(
                        "mma.sync.aligned.m16n8k16.row.col.f32.bf16.bf16.f32 "
                        "{%0,%1,%2,%3}, {%4,%5,%6,%7}, {%8,%9}, {%0,%1,%2,%3};"
                        : "+f"(acc[mt][nt][0]), "+f"(acc[mt][nt][1]),
                          "+f"(acc[mt][nt][2]), "+f"(acc[mt][nt][3])
                        : "r"(a_c[mt][0]), "r"(a_c[mt][1]),
                          "r"(a_c[mt][2]), "r"(a_c[mt][3]),
                          "r"(b_c[nt * 2]), "r"(b_c[nt * 2 + 1]));
            if (kt < 15) {
#pragma unroll
                for (int mt = 0; mt < 2; ++mt)
#pragma unroll
                    for (int i = 0; i < 4; ++i) a_c[mt][i] = a_n[mt][i];
#pragma unroll
                for (int i = 0; i < 4; ++i) b_c[i] = b_n[i];
            }
        }
    }

    const float sc = LN2 * INV_T;
#pragma unroll
    for (int mt = 0; mt < 2; ++mt) {
#pragma unroll
        for (int nt = 0; nt < 2; ++nt) {
            int r = mrow + mt * 16 + (lane >> 2);
            int col = k0 + ncol + nt * 8 + (lane & 3) * 2;
            int base = r * (K_ + 1) + 1 + col;
            out[base]     = lg2f_(256.0f + acc[mt][nt][0]) * sc;
            out[base + 1] = lg2f_(256.0f + acc[mt][nt][1]) * sc;
            int base2 = (r + 8) * (K_ + 1) + 1 + col;
            out[base2]     = lg2f_(256.0f + acc[mt][nt][2]) * sc;
            out[base2 + 1] = lg2f_(256.0f + acc[mt][nt][3]) * sc;
        }
    }
}

extern "C" void kernel_launch(void* const* d_in, const int* in_sizes, int n_in,
                              void* d_out, int out_size) {
    const float* img  = (const float*)d_in[0];
    const float* Wf   = (const float*)d_in[1];
    const float* bf   = (const float*)d_in[2];
    const float* Wc   = (const float*)d_in[3];
    const float* bc   = (const float*)d_in[4];
    const float* dist = (const float*)d_in[5];
    const float* q    = (const float*)d_in[6];
    float* out = (float*)d_out;

    static cudaStream_t s1 = nullptr;
    static cudaEvent_t ev0 = nullptr, ev1 = nullptr;
    if (s1 == nullptr) {
        cudaStreamCreateWithFlags(&s1, cudaStreamNonBlocking);
        cudaEventCreateWithFlags(&ev0, cudaEventDisableTiming);
        cudaEventCreateWithFlags(&ev1, cudaEventDisableTiming);
        cudaFuncSetAttribute(lneg_kernel,
                             cudaFuncAttributeMaxDynamicSharedMemorySize, SMTOT);
    }

    // s1: gemm1 (no deps, starts at t=0)  ||  main: prep -> lneg
    // join -> head (needs gemm1's penult; runs after lneg frees the SMs)
    cudaEventRecord(ev0, 0);
    cudaStreamWaitEvent(s1, ev0, 0);
    gemm1_kernel<<<dim3(4, 64), 256, 0, s1>>>(img, Wf);
    cudaEventRecord(ev1, s1);
    prep_kernel<<<N_, C_>>>(dist, out);
    lneg_kernel<<<K_ / 32, 256, SMTOT>>>(q, out);
    cudaStreamWaitEvent(0, ev1, 0);
    head_kernel<<<N_, 1024>>>(Wc, bc, bf, dist, out);
}

// round 10
// speedup vs baseline: 1.2972x; 1.1268x over previous
#include <cuda_runtime.h>
#include <cuda_bf16.h>
#include <cstdint>

#define N_ 128
#define D_ 2048
#define C_ 256
#define K_ 8192
#define NJ 3          // Taylor terms j=1..3 (j=0 handled as +256 constant)

#define LOG2E 1.4426950408889634f
#define LN2   0.6931471805599453f
#define INV_T (1.0f / 0.07f)

__device__ float g_penult[N_ * C_];           // zero-init; head re-zeroes after use
__device__ __nv_bfloat16 g_A[NJ * N_ * C_];   // A_j[n][c] = dist^j / j!

__device__ __forceinline__ float ex2f_(float x) {
    float y; asm("ex2.approx.f32 %0, %1;" : "=f"(y) : "f"(x)); return y;
}
__device__ __forceinline__ float lg2f_(float x) {
    float y; asm("lg2.approx.f32 %0, %1;" : "=f"(y) : "f"(x)); return y;
}
__device__ __forceinline__ uint32_t su32(const void* p) {
    return (uint32_t)__cvta_generic_to_shared(p);
}
__device__ __forceinline__ uint32_t pack_bf2(float a, float b) {
    __nv_bfloat162 v = __floats2bfloat162_rn(a, b);
    return *reinterpret_cast<uint32_t*>(&v);
}

// ---------------------------------------------------------------------------
// prep: A powers (bf16), labels = 0
// ---------------------------------------------------------------------------
__global__ void prep_kernel(const float* __restrict__ dist,
                            float* __restrict__ out) {
    int n = blockIdx.x, c = threadIdx.x;
    float d = dist[n * C_ + c];
    float p = d;
    g_A[(0 * N_ + n) * C_ + c] = __float2bfloat16(p);
    p *= d;
    g_A[(1 * N_ + n) * C_ + c] = __float2bfloat16(p * 0.5f);
    p *= d;
    g_A[(2 * N_ + n) * C_ + c] = __float2bfloat16(p * (1.0f / 6.0f));
    if (c == 0) out[N_ * (K_ + 1) + n] = 0.0f;   // labels
}

// ---------------------------------------------------------------------------
// gemm1: g_penult += img @ W_f  (fp32 split-K, 256 CTAs)
// ---------------------------------------------------------------------------
__global__ void gemm1_kernel(const float* __restrict__ img,
                             const float* __restrict__ Wf) {
    __shared__ float s_img[128][32];   // 16 KB
    int tid = threadIdx.x;
    int c = blockIdx.x * 64 + (tid & 63);
    int rblk = tid >> 6;
    int d0 = blockIdx.y * 32;

    for (int i = tid; i < 128 * 32; i += 256) {
        int r = i >> 5, dd = i & 31;
        s_img[r][dd] = img[r * D_ + d0 + dd];
    }
    __syncthreads();

    float acc[32];
#pragma unroll
    for (int r = 0; r < 32; r++) acc[r] = 0.0f;

    for (int ds = 0; ds < 32; ds += 4) {
        float w0 = Wf[(d0 + ds + 0) * C_ + c];
        float w1 = Wf[(d0 + ds + 1) * C_ + c];
        float w2 = Wf[(d0 + ds + 2) * C_ + c];
        float w3 = Wf[(d0 + ds + 3) * C_ + c];
#pragma unroll
        for (int r = 0; r < 32; r++) {
            float4 v = *reinterpret_cast<const float4*>(&s_img[rblk * 32 + r][ds]);
            acc[r] = fmaf(v.x, w0, acc[r]);
            acc[r] = fmaf(v.y, w1, acc[r]);
            acc[r] = fmaf(v.z, w2, acc[r]);
            acc[r] = fmaf(v.w, w3, acc[r]);
        }
    }
#pragma unroll
    for (int r = 0; r < 32; r++)
        atomicAdd(&g_penult[(rblk * 32 + r) * C_ + c], acc[r]);
}

// ---------------------------------------------------------------------------
// head: split-K x4, block 1024; runs CONCURRENT with lneg (disjoint outputs).
// ---------------------------------------------------------------------------
__global__ __launch_bounds__(1024, 1)
void head_kernel(const float* __restrict__ Wc,
                 const float* __restrict__ bc,
                 const float* __restrict__ bf,
                 const float* __restrict__ dist,
                 float* __restrict__ out) {
    __shared__ float sp[C_];
    __shared__ float part[3][C_];
    __shared__ float sred[8];
    int n = blockIdx.x;
    int tid = threadIdx.x;
    int ks = tid >> 8;        // 0..3 (64 d's each)
    int c = tid & 255;

    if (ks == 0) sp[c] = g_penult[n * C_ + c] + bf[c];
    __syncthreads();
    if (ks == 0) g_penult[n * C_ + c] = 0.0f;   // reset accumulator for replay

    float acc = 0.0f;
    int d0 = ks * 64;
#pragma unroll 16
    for (int d = 0; d < 64; d++)
        acc = fmaf(sp[d0 + d], Wc[(d0 + d) * C_ + c], acc);

    if (ks) part[ks - 1][c] = acc;
    __syncthreads();
    if (ks != 0) return;

    acc += bc[c] + part[0][c] + part[1][c] + part[2][c];

    out[N_ * (K_ + 1) + N_ + n * C_ + c] = acc;   // f_logit

    float v = acc * acc;
#pragma unroll
    for (int o = 16; o; o >>= 1) v += __shfl_xor_sync(0xffffffffu, v, o);
    if ((c & 31) == 0) sred[c >> 5] = v;
    __syncthreads();
    float ss = sred[0] + sred[1] + sred[2] + sred[3] +
               sred[4] + sred[5] + sred[6] + sred[7];
    __syncthreads();

    float inv = 1.0f / fmaxf(sqrtf(ss), 1e-12f);
    float t = dist[n * C_ + c] * acc * inv;
    float e = ex2f_(t * LOG2E);
#pragma unroll
    for (int o = 16; o; o >>= 1) e += __shfl_xor_sync(0xffffffffu, e, o);
    if ((c & 31) == 0) sred[c >> 5] = e;
    __syncthreads();
    if (c == 0) {
        float s = sred[0] + sred[1] + sred[2] + sred[3] +
                  sred[4] + sred[5] + sred[6] + sred[7];
        out[n * (K_ + 1)] = lg2f_(s) * (LN2 * INV_T);
    }
}

// ---------------------------------------------------------------------------
// lneg v3 (unchanged): grid 256 (32-wide k tiles), block 256, 2 CTAs/SM,
// XOR-swizzled flat tiles, pipelined kt loop.
// ---------------------------------------------------------------------------
#define SMB   0
#define SMA   49152
#define SMTOT 114688

__device__ __forceinline__ void ld_a_x4(uint32_t addr, uint32_t* a) {
    asm volatile("ldmatrix.sync.aligned.m8n8.x4.shared.b16 {%0,%1,%2,%3}, [%4];"
                 : "=r"(a[0]), "=r"(a[1]), "=r"(a[2]), "=r"(a[3]) : "r"(addr));
}

__global__ __launch_bounds__(256, 2)
void lneg_kernel(const float* __restrict__ q,
                 float* __restrict__ out) {
    extern __shared__ char smem[];
    uint32_t sb = su32(smem);
    int tid = threadIdx.x;
    int kx = tid & 31, cg = tid >> 5;
    int k0 = blockIdx.x * 32;

    float qv[32];
    float ss = 0.0f;
    {
        const float* qp = q + (size_t)(cg * 32) * K_ + k0 + kx;
#pragma unroll
        for (int i = 0; i < 32; i++) {
            qv[i] = qp[(size_t)i * K_];
            ss = fmaf(qv[i], qv[i], ss);
        }
    }
    float* ssp = (float*)(smem + SMA);
    float* invp = (float*)(smem + SMA + 1024);
    ssp[cg * 32 + kx] = ss;
    __syncthreads();
    if (tid < 32) {
        float s = 0.0f;
#pragma unroll
        for (int g = 0; g < 8; g++) s += ssp[g * 32 + tid];
        invp[tid] = 1.0f / fmaxf(sqrtf(s), 1e-12f);
    }
    __syncthreads();

    {
        float iv = invp[kx];
#pragma unroll
        for (int i = 0; i < 16; ++i) {
            int c2 = cg * 32 + i * 2;
            float b0 = qv[2 * i] * iv, b1 = qv[2 * i + 1] * iv;
            float p0 = b0, p1 = b1;
            uint32_t off = (uint32_t)(kx * 512 + (((c2 >> 3) ^ (kx & 7)) << 4)
                                      + (c2 & 7) * 2);
#pragma unroll
            for (int j = 0; j < NJ; j++) {
                *(uint32_t*)(smem + SMB + j * 16384 + off) = pack_bf2(p0, p1);
                p0 *= b0; p1 *= b1;
            }
        }
    }

    int warp = tid >> 5, lane = tid & 31;
    int mrow = (warp >> 1) * 32;
    int ncol = (warp & 1) * 16;

    float acc[2][2][4];
#pragma unroll
    for (int mt = 0; mt < 2; mt++)
#pragma unroll
        for (int nt = 0; nt < 2; nt++)
#pragma unroll
            for (int i = 0; i < 4; i++) acc[mt][nt][i] = 0.0f;

    int a_row0 = mrow + (lane & 15);
    int a_chL  = lane >> 4;
    int t4 = lane >> 3;
    int b_row = ncol + ((t4 >> 1) << 3) + (lane & 7);
    int b_chL = t4 & 1;

    for (int j = 0; j < NJ; ++j) {
        __syncthreads();
        const uint4* Asrc = (const uint4*)(g_A + (size_t)j * N_ * C_);
#pragma unroll
        for (int t = 0; t < 16; ++t) {
            int lin = t * 256 + tid;
            int m = lin >> 5;
            int ch = lin & 31;
            *(uint4*)(smem + SMA + m * 512 + ((ch ^ (m & 7)) << 4)) = Asrc[lin];
        }
        __syncthreads();

        uint32_t Ab = sb + SMA;
        uint32_t Bb = sb + SMB + (uint32_t)(j * 16384);

        uint32_t a_c[2][4], b_c[4], a_n[2][4], b_n[4];
#pragma unroll
        for (int mt = 0; mt < 2; ++mt) {
            int row = a_row0 + mt * 16;
            ld_a_x4(Ab + row * 512 + (((a_chL ^ (row & 7)) << 4)), a_c[mt]);
        }
        ld_a_x4(Bb + b_row * 512 + (((b_chL ^ (b_row & 7)) << 4)), b_c);

#pragma unroll
        for (int kt = 0; kt < 16; ++kt) {
            if (kt < 15) {
                int ch = (kt + 1) * 2;
#pragma unroll
                for (int mt = 0; mt < 2; ++mt) {
                    int row = a_row0 + mt * 16;
                    ld_a_x4(Ab + row * 512 + ((((ch + a_chL) ^ (row & 7)) << 4)), a_n[mt]);
                }
                ld_a_x4(Bb + b_row * 512 + ((((ch + b_chL) ^ (b_row & 7)) << 4)), b_n);
            }
#pragma unroll
            for (int mt = 0; mt < 2; ++mt)
#pragma unroll
                for (int nt = 0; nt < 2; ++nt)
                    asm volatile(
                        "mma.sync.aligned.m16n8k16.row.col.f32.bf16.bf16.f32 "
                        "{%0,%1,%2,%3}, {%4,%5,%6,%7}, {%8,%9}, {%0,%1,%2,%3};"
                        : "+f"(acc[mt][nt][0]), "+f"(acc[mt][nt][1]),
                          "+f"(acc[mt][nt][2]), "+f"(acc[mt][nt][3])
                        : "r"(a_c[mt][0]), "r"(a_c[mt][1]),
                          "r"(a_c[mt][2]), "r"(a_c[mt][3]),
                          "r"(b_c[nt * 2]), "r"(b_c[nt * 2 + 1]));
            if (kt < 15) {
#pragma unroll
                for (int mt = 0; mt < 2; ++mt)
#pragma unroll
                    for (int i = 0; i < 4; ++i) a_c[mt][i] = a_n[mt][i];
#pragma unroll
                for (int i = 0; i < 4; ++i) b_c[i] = b_n[i];
            }
        }
    }

    const float sc = LN2 * INV_T;
#pragma unroll
    for (int mt = 0; mt < 2; ++mt) {
#pragma unroll
        for (int nt = 0; nt < 2; ++nt) {
            int r = mrow + mt * 16 + (lane >> 2);
            int col = k0 + ncol + nt * 8 + (lane & 3) * 2;
            int base = r * (K_ + 1) + 1 + col;
            out[base]     = lg2f_(256.0f + acc[mt][nt][0]) * sc;
            out[base + 1] = lg2f_(256.0f + acc[mt][nt][1]) * sc;
            int base2 = (r + 8) * (K_ + 1) + 1 + col;
            out[base2]     = lg2f_(256.0f + acc[mt][nt][2]) * sc;
            out[base2 + 1] = lg2f_(256.0f + acc[mt][nt][3]) * sc;
        }
    }
}

extern "C" void kernel_launch(void* const* d_in, const int* in_sizes, int n_in,
                              void* d_out, int out_size) {
    const float* img  = (const float*)d_in[0];
    const float* Wf   = (const float*)d_in[1];
    const float* bf   = (const float*)d_in[2];
    const float* Wc   = (const float*)d_in[3];
    const float* bc   = (const float*)d_in[4];
    const float* dist = (const float*)d_in[5];
    const float* q    = (const float*)d_in[6];
    float* out = (float*)d_out;

    static cudaStream_t s1 = nullptr;
    static cudaEvent_t ev0 = nullptr, ev1 = nullptr;
    if (s1 == nullptr) {
        cudaStreamCreateWithFlags(&s1, cudaStreamNonBlocking);
        cudaEventCreateWithFlags(&ev0, cudaEventDisableTiming);
        cudaEventCreateWithFlags(&ev1, cudaEventDisableTiming);
        cudaFuncSetAttribute(lneg_kernel,
                             cudaFuncAttributeMaxDynamicSharedMemorySize, SMTOT);
    }

    // main: prep -> lneg          (l_neg columns)
    // s1:   gemm1 -> head         (f_logit, l_pos, labels via prep)
    // single join at the end; the two chains touch disjoint output regions.
    cudaEventRecord(ev0, 0);
    cudaStreamWaitEvent(s1, ev0, 0);
    gemm1_kernel<<<dim3(4, 64), 256, 0, s1>>>(img, Wf);
    head_kernel<<<N_, 1024, 0, s1>>>(Wc, bc, bf, dist, out);
    cudaEventRecord(ev1, s1);
    prep_kernel<<<N_, C_>>>(dist, out);
    lneg_kernel<<<K_ / 32, 256, SMTOT>>>(q, out);
    cudaStreamWaitEvent(0, ev1, 0);
}

// round 11
// speedup vs baseline: 1.3708x; 1.0568x over previous
#include <cuda_runtime.h>
#include <cuda_bf16.h>
#include <cstdint>

#define N_ 128
#define D_ 2048
#define C_ 256
#define K_ 8192
#define NJ 3          // Taylor terms j=1..3 (j=0 handled as +256 constant)

#define LOG2E 1.4426950408889634f
#define LN2   0.6931471805599453f
#define INV_T (1.0f / 0.07f)

__device__ float g_penult[N_ * C_];           // zero-init; head re-zeroes after use
__device__ __nv_bfloat16 g_A[NJ * N_ * C_];   // A_j[n][c] = dist^j / j!

__device__ __forceinline__ float ex2f_(float x) {
    float y; asm("ex2.approx.f32 %0, %1;" : "=f"(y) : "f"(x)); return y;
}
__device__ __forceinline__ float lg2f_(float x) {
    float y; asm("lg2.approx.f32 %0, %1;" : "=f"(y) : "f"(x)); return y;
}
__device__ __forceinline__ uint32_t su32(const void* p) {
    return (uint32_t)__cvta_generic_to_shared(p);
}

// ---------------------------------------------------------------------------
// prep: A powers (bf16), labels = 0
// ---------------------------------------------------------------------------
__global__ void prep_kernel(const float* __restrict__ dist,
                            float* __restrict__ out) {
    int n = blockIdx.x, c = threadIdx.x;
    float d = dist[n * C_ + c];
    float p = d;
    g_A[(0 * N_ + n) * C_ + c] = __float2bfloat16(p);
    p *= d;
    g_A[(1 * N_ + n) * C_ + c] = __float2bfloat16(p * 0.5f);
    p *= d;
    g_A[(2 * N_ + n) * C_ + c] = __float2bfloat16(p * (1.0f / 6.0f));
    if (c == 0) out[N_ * (K_ + 1) + n] = 0.0f;   // labels
}

// ---------------------------------------------------------------------------
// gemm1: g_penult += img @ W_f  (fp32 split-K, 256 CTAs)
// ---------------------------------------------------------------------------
__global__ void gemm1_kernel(const float* __restrict__ img,
                             const float* __restrict__ Wf) {
    __shared__ float s_img[128][32];   // 16 KB
    int tid = threadIdx.x;
    int c = blockIdx.x * 64 + (tid & 63);
    int rblk = tid >> 6;
    int d0 = blockIdx.y * 32;

    for (int i = tid; i < 128 * 32; i += 256) {
        int r = i >> 5, dd = i & 31;
        s_img[r][dd] = img[r * D_ + d0 + dd];
    }
    __syncthreads();

    float acc[32];
#pragma unroll
    for (int r = 0; r < 32; r++) acc[r] = 0.0f;

    for (int ds = 0; ds < 32; ds += 4) {
        float w0 = Wf[(d0 + ds + 0) * C_ + c];
        float w1 = Wf[(d0 + ds + 1) * C_ + c];
        float w2 = Wf[(d0 + ds + 2) * C_ + c];
        float w3 = Wf[(d0 + ds + 3) * C_ + c];
#pragma unroll
        for (int r = 0; r < 32; r++) {
            float4 v = *reinterpret_cast<const float4*>(&s_img[rblk * 32 + r][ds]);
            acc[r] = fmaf(v.x, w0, acc[r]);
            acc[r] = fmaf(v.y, w1, acc[r]);
            acc[r] = fmaf(v.z, w2, acc[r]);
            acc[r] = fmaf(v.w, w3, acc[r]);
        }
    }
#pragma unroll
    for (int r = 0; r < 32; r++)
        atomicAdd(&g_penult[(rblk * 32 + r) * C_ + c], acc[r]);
}

// ---------------------------------------------------------------------------
// head: split-K x4, block 1024; concurrent with lneg (disjoint outputs).
// ---------------------------------------------------------------------------
__global__ __launch_bounds__(1024, 1)
void head_kernel(const float* __restrict__ Wc,
                 const float* __restrict__ bc,
                 const float* __restrict__ bf,
                 const float* __restrict__ dist,
                 float* __restrict__ out) {
    __shared__ float sp[C_];
    __shared__ float part[3][C_];
    __shared__ float sred[8];
    int n = blockIdx.x;
    int tid = threadIdx.x;
    int ks = tid >> 8;        // 0..3 (64 d's each)
    int c = tid & 255;

    if (ks == 0) sp[c] = g_penult[n * C_ + c] + bf[c];
    __syncthreads();
    if (ks == 0) g_penult[n * C_ + c] = 0.0f;   // reset accumulator for replay

    float acc = 0.0f;
    int d0 = ks * 64;
#pragma unroll 16
    for (int d = 0; d < 64; d++)
        acc = fmaf(sp[d0 + d], Wc[(d0 + d) * C_ + c], acc);

    if (ks) part[ks - 1][c] = acc;
    __syncthreads();
    if (ks != 0) return;

    acc += bc[c] + part[0][c] + part[1][c] + part[2][c];

    out[N_ * (K_ + 1) + N_ + n * C_ + c] = acc;   // f_logit

    float v = acc * acc;
#pragma unroll
    for (int o = 16; o; o >>= 1) v += __shfl_xor_sync(0xffffffffu, v, o);
    if ((c & 31) == 0) sred[c >> 5] = v;
    __syncthreads();
    float ss = sred[0] + sred[1] + sred[2] + sred[3] +
               sred[4] + sred[5] + sred[6] + sred[7];
    __syncthreads();

    float inv = 1.0f / fmaxf(sqrtf(ss), 1e-12f);
    float t = dist[n * C_ + c] * acc * inv;
    float e = ex2f_(t * LOG2E);
#pragma unroll
    for (int o = 16; o; o >>= 1) e += __shfl_xor_sync(0xffffffffu, e, o);
    if ((c & 31) == 0) sred[c >> 5] = e;
    __syncthreads();
    if (c == 0) {
        float s = sred[0] + sred[1] + sred[2] + sred[3] +
                  sred[4] + sred[5] + sred[6] + sred[7];
        out[n * (K_ + 1)] = lg2f_(s) * (LN2 * INV_T);
    }
}

// ---------------------------------------------------------------------------
// lneg v4: grid 256 (32-wide k tiles), block 256, 2 CTAs/SM.
// smem 80KB: A slot 64KB + ONE B slot 16KB (rebuilt per j from registers:
// b and running power p kept as bf16x2 regs). Leaves 67KB/SM so gemm1/head
// CTAs co-reside and truly overlap.
// ---------------------------------------------------------------------------
#define SMA   0
#define SMB   65536
#define SMTOT 81920

__device__ __forceinline__ void ld_a_x4(uint32_t addr, uint32_t* a) {
    asm volatile("ldmatrix.sync.aligned.m8n8.x4.shared.b16 {%0,%1,%2,%3}, [%4];"
                 : "=r"(a[0]), "=r"(a[1]), "=r"(a[2]), "=r"(a[3]) : "r"(addr));
}

__global__ __launch_bounds__(256, 2)
void lneg_kernel(const float* __restrict__ q,
                 float* __restrict__ out) {
    extern __shared__ char smem[];
    uint32_t sb = su32(smem);
    int tid = threadIdx.x;
    int kx = tid & 31, cg = tid >> 5;
    int k0 = blockIdx.x * 32;

    // ---- q column-slice -> regs; sum of squares ----
    float qv[32];
    float ss = 0.0f;
    {
        const float* qp = q + (size_t)(cg * 32) * K_ + k0 + kx;
#pragma unroll
        for (int i = 0; i < 32; i++) {
            qv[i] = qp[(size_t)i * K_];
            ss = fmaf(qv[i], qv[i], ss);
        }
    }
    float* ssp = (float*)(smem + SMA);          // alias into A region (pre-loop)
    float* invp = (float*)(smem + SMA + 1024);
    ssp[cg * 32 + kx] = ss;
    __syncthreads();
    if (tid < 32) {
        float s = 0.0f;
#pragma unroll
        for (int g = 0; g < 8; g++) s += ssp[g * 32 + tid];
        invp[tid] = 1.0f / fmaxf(sqrtf(s), 1e-12f);
    }
    __syncthreads();

    // ---- b = q*inv and running power p, packed bf16x2 in regs ----
    __nv_bfloat162 b2[16], p2[16];
    {
        float iv = invp[kx];
#pragma unroll
        for (int i = 0; i < 16; ++i) {
            b2[i] = __floats2bfloat162_rn(qv[2 * i] * iv, qv[2 * i + 1] * iv);
            p2[i] = b2[i];
        }
    }

    int warp = tid >> 5, lane = tid & 31;
    int mrow = (warp >> 1) * 32;
    int ncol = (warp & 1) * 16;

    float acc[2][2][4];
#pragma unroll
    for (int mt = 0; mt < 2; mt++)
#pragma unroll
        for (int nt = 0; nt < 2; nt++)
#pragma unroll
            for (int i = 0; i < 4; i++) acc[mt][nt][i] = 0.0f;

    int a_row0 = mrow + (lane & 15);
    int a_chL  = lane >> 4;
    int t4 = lane >> 3;
    int b_row = ncol + ((t4 >> 1) << 3) + (lane & 7);
    int b_chL = t4 & 1;

    uint32_t Ab = sb + SMA;
    uint32_t Bb = sb + SMB;

    for (int j = 0; j < NJ; ++j) {
        __syncthreads();   // inv consumed (j=0) / prior A+B consumption done
        // stage A_j [128 x 256] -> swizzled tile
        const uint4* Asrc = (const uint4*)(g_A + (size_t)j * N_ * C_);
#pragma unroll
        for (int t = 0; t < 16; ++t) {
            int lin = t * 256 + tid;
            int m = lin >> 5;
            int ch = lin & 31;
            *(uint4*)(smem + SMA + m * 512 + ((ch ^ (m & 7)) << 4)) = Asrc[lin];
        }
        // build B_j = b^(j+1) into the single B slot from registers
#pragma unroll
        for (int i = 0; i < 16; ++i) {
            int c2 = cg * 32 + i * 2;
            uint32_t off = (uint32_t)(kx * 512 + (((c2 >> 3) ^ (kx & 7)) << 4)
                                      + (c2 & 7) * 2);
            *(uint32_t*)(smem + SMB + off) = *(uint32_t*)&p2[i];
            p2[i] = __hmul2(p2[i], b2[i]);
        }
        __syncthreads();

        uint32_t a_c[2][4], b_c[4], a_n[2][4], b_n[4];
#pragma unroll
        for (int mt = 0; mt < 2; ++mt) {
            int row = a_row0 + mt * 16;
            ld_a_x4(Ab + row * 512 + (((a_chL ^ (row & 7)) << 4)), a_c[mt]);
        }
        ld_a_x4(Bb + b_row * 512 + (((b_chL ^ (b_row & 7)) << 4)), b_c);

#pragma unroll
        for (int kt = 0; kt < 16; ++kt) {
            if (kt < 15) {
                int ch = (kt + 1) * 2;
#pragma unroll
                for (int mt = 0; mt < 2; ++mt) {
                    int row = a_row0 + mt * 16;
                    ld_a_x4(Ab + row * 512 + ((((ch + a_chL) ^ (row & 7)) << 4)), a_n[mt]);
                }
                ld_a_x4(Bb + b_row * 512 + ((((ch + b_chL) ^ (b_row & 7)) << 4)), b_n);
            }
#pragma unroll
            for (int mt = 0; mt < 2; ++mt)
#pragma unroll
                for (int nt = 0; nt < 2; ++nt)
                    asm volatile(
                        "mma.sync.aligned.m16n8k16.row.col.f32.bf16.bf16.f32 "
                        "{%0,%1,%2,%3}, {%4,%5,%6,%7}, {%8,%9}, {%0,%1,%2,%3};"
                        : "+f"(acc[mt][nt][0]), "+f"(acc[mt][nt][1]),
                          "+f"(acc[mt][nt][2]), "+f"(acc[mt][nt][3])
                        : "r"(a_c[mt][0]), "r"(a_c[mt][1]),
                          "r"(a_c[mt][2]), "r"(a_c[mt][3]),
                          "r"(b_c[nt * 2]), "r"(b_c[nt * 2 + 1]));
            if (kt < 15) {
#pragma unroll
                for (int mt = 0; mt < 2; ++mt)
#pragma unroll
                    for (int i = 0; i < 4; ++i) a_c[mt][i] = a_n[mt][i];
#pragma unroll
                for (int i = 0; i < 4; ++i) b_c[i] = b_n[i];
            }
        }
    }

    const float sc = LN2 * INV_T;
#pragma unroll
    for (int mt = 0; mt < 2; ++mt) {
#pragma unroll
        for (int nt = 0; nt < 2; ++nt) {
            int r = mrow + mt * 16 + (lane >> 2);
            int col = k0 + ncol + nt * 8 + (lane & 3) * 2;
            int base = r * (K_ + 1) + 1 + col;
            out[base]     = lg2f_(256.0f + acc[mt][nt][0]) * sc;
            out[base + 1] = lg2f_(256.0f + acc[mt][nt][1]) * sc;
            int base2 = (r + 8) * (K_ + 1) + 1 + col;
            out[base2]     = lg2f_(256.0f + acc[mt][nt][2]) * sc;
            out[base2 + 1] = lg2f_(256.0f + acc[mt][nt][3]) * sc;
        }
    }
}

extern "C" void kernel_launch(void* const* d_in, const int* in_sizes, int n_in,
                              void* d_out, int out_size) {
    const float* img  = (const float*)d_in[0];
    const float* Wf   = (const float*)d_in[1];
    const float* bf   = (const float*)d_in[2];
    const float* Wc   = (const float*)d_in[3];
    const float* bc   = (const float*)d_in[4];
    const float* dist = (const float*)d_in[5];
    const float* q    = (const float*)d_in[6];
    float* out = (float*)d_out;

    static cudaStream_t s1 = nullptr;
    static cudaEvent_t ev0 = nullptr, ev1 = nullptr;
    if (s1 == nullptr) {
        cudaStreamCreateWithFlags(&s1, cudaStreamNonBlocking);
        cudaEventCreateWithFlags(&ev0, cudaEventDisableTiming);
        cudaEventCreateWithFlags(&ev1, cudaEventDisableTiming);
        cudaFuncSetAttribute(lneg_kernel,
                             cudaFuncAttributeMaxDynamicSharedMemorySize, SMTOT);
    }

    // main: prep -> lneg          (l_neg columns)
    // s1:   gemm1 -> head         (f_logit, l_pos)
    // lneg now leaves 67KB smem/SM free so the s1 chain co-resides.
    cudaEventRecord(ev0, 0);
    cudaStreamWaitEvent(s1, ev0, 0);
    gemm1_kernel<<<dim3(4, 64), 256, 0, s1>>>(img, Wf);
    head_kernel<<<N_, 1024, 0, s1>>>(Wc, bc, bf, dist, out);
    cudaEventRecord(ev1, s1);
    prep_kernel<<<N_, C_>>>(dist, out);
    lneg_kernel<<<K_ / 32, 256, SMTOT>>>(q, out);
    cudaStreamWaitEvent(0, ev1, 0);
}